// round 17
// baseline (speedup 1.0000x reference)
#include <cuda_runtime.h>
#include <cuda_bf16.h>
#include <cstdint>

#define T_STEPS 512
#define BATCH   64
#define DIN     1024
#define HID     128
#define GATES   512   // 4*HID

// Scratch: x1[t][b][g] = feats @ W_ih1^T + b_ih1 + b_hh1   (64 MB)
__device__ float g_x1[(size_t)T_STEPS * BATCH * GATES];

// ---------------------------------------------------------------------------
// helpers
// ---------------------------------------------------------------------------
__device__ __forceinline__ uint32_t s2u(const void* p){
    uint32_t a;
    asm("{ .reg .u64 t; cvta.to.shared.u64 t, %1; cvt.u32.u64 %0, t; }" : "=r"(a) : "l"(p));
    return a;
}
__device__ __forceinline__ void ldsm4(uint32_t* r, uint32_t addr){
    asm volatile("ldmatrix.sync.aligned.m8n8.x4.shared.b16 {%0,%1,%2,%3}, [%4];"
        : "=r"(r[0]), "=r"(r[1]), "=r"(r[2]), "=r"(r[3]) : "r"(addr));
}
__device__ __forceinline__ void mma16816(float* c, const uint32_t* a, const uint32_t* b){
    asm volatile("mma.sync.aligned.m16n8k16.row.col.f32.bf16.bf16.f32 "
        "{%0,%1,%2,%3}, {%4,%5,%6,%7}, {%8,%9}, {%0,%1,%2,%3};"
        : "+f"(c[0]), "+f"(c[1]), "+f"(c[2]), "+f"(c[3])
        : "r"(a[0]), "r"(a[1]), "r"(a[2]), "r"(a[3]), "r"(b[0]), "r"(b[1]));
}
// hi bf16 pair = truncated top-16 bits of (x,y)
__device__ __forceinline__ uint2 hi_pair(float4 v){
    uint32_t x = __float_as_uint(v.x), y = __float_as_uint(v.y);
    uint32_t z = __float_as_uint(v.z), w = __float_as_uint(v.w);
    uint32_t h0, h1;
    asm("prmt.b32 %0, %1, %2, 0x7632;" : "=r"(h0) : "r"(x), "r"(y));
    asm("prmt.b32 %0, %1, %2, 0x7632;" : "=r"(h1) : "r"(z), "r"(w));
    return make_uint2(h0, h1);
}
// lo residual pair (exact subtract of truncated hi, then rn to bf16)
__device__ __forceinline__ uint2 lo_pair(float4 v){
    float lx = v.x - __uint_as_float(__float_as_uint(v.x) & 0xFFFF0000u);
    float ly = v.y - __uint_as_float(__float_as_uint(v.y) & 0xFFFF0000u);
    float lz = v.z - __uint_as_float(__float_as_uint(v.z) & 0xFFFF0000u);
    float lw = v.w - __uint_as_float(__float_as_uint(v.w) & 0xFFFF0000u);
    uint32_t l0, l1;
    asm("cvt.rn.bf16x2.f32 %0, %1, %2;" : "=r"(l0) : "f"(ly), "f"(lx));
    asm("cvt.rn.bf16x2.f32 %0, %1, %2;" : "=r"(l1) : "f"(lw), "f"(lz));
    return make_uint2(l0, l1);
}
__device__ __forceinline__ unsigned long long fma2(unsigned long long a,
        unsigned long long b, unsigned long long c){
    unsigned long long d;
    asm("fma.rn.f32x2 %0, %1, %2, %3;" : "=l"(d) : "l"(a), "l"(b), "l"(c));
    return d;
}
__device__ __forceinline__ unsigned long long packf2(float x, float y){
    unsigned long long r;
    asm("mov.b64 %0, {%1, %2};" : "=l"(r) : "f"(x), "f"(y));
    return r;
}
__device__ __forceinline__ float hsum2(unsigned long long v){
    return __uint_as_float((uint32_t)v) + __uint_as_float((uint32_t)(v >> 32));
}
__device__ __forceinline__ float sigf(float x){
    return __fdividef(1.0f, 1.0f + __expf(-x));
}
__device__ __forceinline__ float tanhfast(float x){
    return 2.0f * __fdividef(1.0f, 1.0f + __expf(-2.0f * x)) - 1.0f;
}

// ---------------------------------------------------------------------------
// Kernel 1: x1 GEMM via split-bf16 mma.sync (3 passes: hh + lh + hl).
// (unchanged — 263us, protected)
// ---------------------------------------------------------------------------
#define PITCH 80
#define TILE_B (128 * PITCH)      // 10240
#define O_AHI 0
#define O_ALO (1 * TILE_B)
#define O_BHI (2 * TILE_B)
#define O_BLO (3 * TILE_B)
#define BUFB  (4 * TILE_B)        // 40960
#define GSMEM (2 * BUFB)          // 81920

__global__ __launch_bounds__(256, 1) void x1_gemm_hmma(
    const float* __restrict__ A,
    const float* __restrict__ W,
    const float* __restrict__ bih,
    const float* __restrict__ bhh)
{
    extern __shared__ __align__(128) char smg[];
    __shared__ float biasS[128];
    const int tid  = threadIdx.x;
    const int lane = tid & 31, wid = tid >> 5;
    const int wm = wid & 3, wn = wid >> 2;
    const int m0 = blockIdx.y << 7, n0 = blockIdx.x << 7;

    if (tid < 128) biasS[tid] = bih[n0 + tid] + bhh[n0 + tid];

    const int lrow = tid >> 3;
    const int lc4  = tid & 7;
    const float* Abase = A + (size_t)(m0 + lrow) * DIN + lc4 * 4;
    const float* Wbase = W + (size_t)(n0 + lrow) * DIN + lc4 * 4;
    const int soff = lrow * PITCH + lc4 * 8;

    const uint32_t sbase = s2u(smg);
    const uint32_t a_off = (uint32_t)((wm * 32 + (lane & 15)) * PITCH + (lane >> 4) * 16);
    const uint32_t b_off = (uint32_t)((wn * 64 + (lane & 7) + 8 * (lane >> 4)) * PITCH
                                      + ((lane >> 3) & 1) * 16);

    float c[2][8][4];
    #pragma unroll
    for (int i = 0; i < 2; i++)
        #pragma unroll
        for (int j = 0; j < 8; j++)
            #pragma unroll
            for (int k = 0; k < 4; k++) c[i][j][k] = 0.f;

    float4 ra[4], rw[4];
    #pragma unroll
    for (int i = 0; i < 4; i++){
        ra[i] = *(const float4*)(Abase + (size_t)(32 * i) * DIN);
        rw[i] = *(const float4*)(Wbase + (size_t)(32 * i) * DIN);
    }
    #pragma unroll
    for (int i = 0; i < 4; i++){
        int off = soff + i * 32 * PITCH;
        *(uint2*)(smg + O_AHI + off) = hi_pair(ra[i]);
        *(uint2*)(smg + O_ALO + off) = lo_pair(ra[i]);
        *(uint2*)(smg + O_BHI + off) = hi_pair(rw[i]);
        *(uint2*)(smg + O_BLO + off) = lo_pair(rw[i]);
    }
    __syncthreads();

    for (int ci = 0; ci < 32; ci++){
        const uint32_t buf = sbase + (uint32_t)(ci & 1) * BUFB;
        if (ci < 31){
            #pragma unroll
            for (int i = 0; i < 4; i++){
                ra[i] = *(const float4*)(Abase + (size_t)(32 * i) * DIN + (ci + 1) * 32);
                rw[i] = *(const float4*)(Wbase + (size_t)(32 * i) * DIN + (ci + 1) * 32);
            }
        }
        #pragma unroll
        for (int kk = 0; kk < 2; kk++){
            uint32_t ah0[4], ah1[4], al0[4], al1[4], bh[4][4], bl[4][4];
            const uint32_t ka = a_off + kk * 32;
            const uint32_t kb = b_off + kk * 32;
            ldsm4(ah0, buf + O_AHI + ka);
            ldsm4(ah1, buf + O_AHI + ka + 16 * PITCH);
            ldsm4(al0, buf + O_ALO + ka);
            ldsm4(al1, buf + O_ALO + ka + 16 * PITCH);
            #pragma unroll
            for (int q2 = 0; q2 < 4; q2++){
                ldsm4(bh[q2], buf + O_BHI + kb + q2 * 16 * PITCH);
                ldsm4(bl[q2], buf + O_BLO + kb + q2 * 16 * PITCH);
            }
            #pragma unroll
            for (int nt = 0; nt < 8; nt++){
                const uint32_t* bhp = &bh[nt >> 1][(nt & 1) * 2];
                const uint32_t* blp = &bl[nt >> 1][(nt & 1) * 2];
                mma16816(c[0][nt], ah0, bhp);
                mma16816(c[1][nt], ah1, bhp);
                mma16816(c[0][nt], al0, bhp);
                mma16816(c[1][nt], al1, bhp);
                mma16816(c[0][nt], ah0, blp);
                mma16816(c[1][nt], ah1, blp);
            }
        }
        if (ci < 31){
            char* b = smg + ((ci + 1) & 1) * BUFB;
            #pragma unroll
            for (int i = 0; i < 4; i++){
                int off = soff + i * 32 * PITCH;
                *(uint2*)(b + O_AHI + off) = hi_pair(ra[i]);
                *(uint2*)(b + O_ALO + off) = lo_pair(ra[i]);
                *(uint2*)(b + O_BHI + off) = hi_pair(rw[i]);
                *(uint2*)(b + O_BLO + off) = lo_pair(rw[i]);
            }
        }
        __syncthreads();
    }

    const int gr = lane >> 2;
    const int gc = (lane & 3) * 2;
    #pragma unroll
    for (int mt = 0; mt < 2; mt++){
        #pragma unroll
        for (int nt = 0; nt < 8; nt++){
            const int n = wn * 64 + nt * 8 + gc;
            const float b0 = biasS[n], b1 = biasS[n + 1];
            #pragma unroll
            for (int rr = 0; rr < 2; rr++){
                const int m = m0 + wm * 32 + mt * 16 + gr + rr * 8;
                const int bb = m >> 9;
                const int tt = m & 511;
                float2 o = make_float2(c[mt][nt][rr * 2 + 0] + b0,
                                       c[mt][nt][rr * 2 + 1] + b1);
                *(float2*)(g_x1 + ((size_t)tt * BATCH + bb) * GATES + n0 + n) = o;
            }
        }
    }
}

// ---------------------------------------------------------------------------
// Kernel 2: recurrence, k-split-4 (r15) + BULK h-exchange (r17).
// Gate units STS h locally; after __syncthreads, 12 threads issue 128B
// cp.async.bulk.shared::cluster copies (3 peers x {h1,h2}x{bu0,bu1}) with
// mbarrier complete_tx at the peer. Incoming per CTA per step: 12 DMAs +
// 12 tx updates instead of 512 scalar st.async + 512 updates.
// ---------------------------------------------------------------------------
__device__ __forceinline__ void mbar_expect(uint32_t mb, uint32_t tx){
    asm volatile("mbarrier.arrive.expect_tx.shared.b64 _, [%0], %1;"
                 :: "r"(mb), "r"(tx) : "memory");
}
__device__ __forceinline__ void mbar_wait_c(uint32_t mb, uint32_t parity){
    asm volatile(
        "{\n\t.reg .pred P;\n\t"
        "WL_%=:\n\t"
        "mbarrier.try_wait.parity.acquire.cluster.shared::cta.b64 P, [%0], %1;\n\t"
        "@!P bra WL_%=;\n\t"
        "}\n" :: "r"(mb), "r"(parity) : "memory");
}
// 128B smem->peer-smem bulk copy, tx-completing the peer's mbarrier
__device__ __forceinline__ void bulk128(uint32_t local_blk, uint32_t local_mbar,
                                        uint32_t pr){
    uint32_t rd, rb;
    asm volatile("mapa.shared::cluster.u32 %0, %1, %2;" : "=r"(rd) : "r"(local_blk), "r"(pr));
    asm volatile("mapa.shared::cluster.u32 %0, %1, %2;" : "=r"(rb) : "r"(local_mbar), "r"(pr));
    asm volatile("cp.async.bulk.shared::cluster.shared::cta.mbarrier::complete_tx::bytes "
                 "[%0], [%1], %2, [%3];"
                 :: "r"(rd), "r"(local_blk), "r"(128u), "r"(rb) : "memory");
}

#define HPAD 36   // padded chunk stride (floats); 4 chunks = 144

__global__ void __cluster_dims__(4,1,1) __launch_bounds__(256, 1)
lstm_rec_kernel(const float* __restrict__ Whh1,
                const float* __restrict__ Wih2,
                const float* __restrict__ Whh2,
                const float* __restrict__ bih2,
                const float* __restrict__ bhh2,
                float* __restrict__ out)
{
    __shared__ __align__(16) float h1s[2][2][4 * HPAD];
    __shared__ __align__(16) float h2s[2][2][4 * HPAD];
    __shared__ __align__(16) unsigned long long mbar[2];

    const int tid  = threadIdx.x;
    const int w    = tid >> 5;
    const int lane = tid & 31;
    const int c    = lane & 3;          // k-chunk: [32c, 32c+32)
    const int slot = lane >> 2;         // 0..7
    const int jl   = slot & 3;
    const int gp   = slot >> 2;         // gate pair: gates {2gp, 2gp+1}
    const int Lu   = (lane >> 1) & 1;   // gate-unit layer (lane<16)
    const int bu   = lane & 1;          // gate-unit batch
    uint32_t rank;
    asm("mov.u32 %0, %%cluster_ctarank;" : "=r"(rank));
    const int b0     = (blockIdx.x >> 2) * 2;
    const int j_cta  = w * 4 + jl;                 // 0..31 within CTA slice
    const int j_glob = (int)rank * 32 + j_cta;
    const uint32_t mba = (uint32_t)__cvta_generic_to_shared(&mbar[0]);

    // bulk-copy assignment: lanes 0-1 of warps 0-5 -> 12 copies
    const int cp_idx  = w * 2 + lane;               // valid when lane<2 && w<6
    const int cp_peer = cp_idx >> 2;                // 0..2
    const uint32_t cp_pr = (uint32_t)(cp_peer + (cp_peer >= (int)rank ? 1 : 0));
    const int cp_arr  = (cp_idx >> 1) & 1;          // 0: h1, 1: h2
    const int cp_bu   = cp_idx & 1;

    // register-resident packed weights: [gate-in-pair][k-pair], 96 b64 total
    unsigned long long w1p[2][16], w2p[2][16], w3p[2][16];
    #pragma unroll
    for (int gg = 0; gg < 2; gg++){
        const int row = (2 * gp + gg) * 128 + j_glob;
        const float4* p1 = (const float4*)(Whh1 + (size_t)row * HID + c * 32);
        const float4* p2 = (const float4*)(Wih2 + (size_t)row * HID + c * 32);
        const float4* p3 = (const float4*)(Whh2 + (size_t)row * HID + c * 32);
        #pragma unroll
        for (int q = 0; q < 8; q++){
            float4 v1 = p1[q], v2 = p2[q], v3 = p3[q];
            w1p[gg][2*q] = packf2(v1.x, v1.y);  w1p[gg][2*q+1] = packf2(v1.z, v1.w);
            w2p[gg][2*q] = packf2(v2.x, v2.y);  w2p[gg][2*q+1] = packf2(v2.z, v2.w);
            w3p[gg][2*q] = packf2(v3.x, v3.y);  w3p[gg][2*q+1] = packf2(v3.z, v3.w);
        }
    }

    // gate-unit constants (lane<16): layer-2 units need 4 bias values
    float b2r0 = 0.f, b2r1 = 0.f, b2r2 = 0.f, b2r3 = 0.f;
    if (lane < 16 && Lu == 1){
        b2r0 = bih2[0 * 128 + j_glob] + bhh2[0 * 128 + j_glob];
        b2r1 = bih2[1 * 128 + j_glob] + bhh2[1 * 128 + j_glob];
        b2r2 = bih2[2 * 128 + j_glob] + bhh2[2 * 128 + j_glob];
        b2r3 = bih2[3 * 128 + j_glob] + bhh2[3 * 128 + j_glob];
    }

    for (int i = tid; i < 2 * 2 * 4 * HPAD; i += 256){
        (&h1s[0][0][0])[i] = 0.f;
        (&h2s[0][0][0])[i] = 0.f;
    }
    if (tid == 0){
        asm volatile("mbarrier.init.shared.b64 [%0], %1;" :: "r"(mba), "r"(1u) : "memory");
        asm volatile("mbarrier.init.shared.b64 [%0], %1;" :: "r"(mba + 8), "r"(1u) : "memory");
        mbar_expect(mba,      768u);   // prologue: h1(0), 3 peers x 2 bu x 128B
        mbar_expect(mba + 8, 1536u);   // step 0 stores h(1): 3 peers x 4 blocks
    }
    __syncthreads();
    asm volatile("barrier.cluster.arrive.aligned;" ::: "memory");
    asm volatile("barrier.cluster.wait.aligned;"   ::: "memory");

    // Prologue: h1(0) from x(0) only; local STS then 6 bulk copies.
    float cst = 0.f;
    float xu0 = 0.f, xu1 = 0.f, xu2 = 0.f, xu3 = 0.f;
    if (lane < 16 && Lu == 0){
        const float* xp = g_x1 + ((size_t)0 * BATCH + b0 + bu) * GATES + j_glob;
        float p0 = xp[0], p2 = xp[256], p3 = xp[384];
        cst = sigf(p0) * tanhfast(p2);
        float h = sigf(p3) * tanhfast(cst);
        h1s[0][bu][(int)rank * HPAD + j_cta] = h;
        const float* xq = g_x1 + ((size_t)1 * BATCH + b0 + bu) * GATES + j_glob;
        xu0 = xq[0]; xu1 = xq[128]; xu2 = xq[256]; xu3 = xq[384];
    }
    __syncthreads();
    if (lane < 2 && w < 6 && cp_arr == 0){   // 6 copies: h1 x bu x 3 peers
        uint32_t blk = (uint32_t)__cvta_generic_to_shared(
            &h1s[0][cp_bu][(int)rank * HPAD]);
        bulk128(blk, mba, cp_pr);
    }
    mbar_wait_c(mba, 0);
    if (tid == 0) mbar_expect(mba, 1536u);   // re-arm for step 1

    int cur = 0;
    for (int t = 0; t < T_STEPS; t++){
        const int nxt = cur ^ 1;
        const int b   = (t + 1) & 1;                 // barrier fed this step
        const uint32_t mbt = mba + (uint32_t)(b << 3);

        // prefetch x(t+2) early so it overlaps the FMA window
        float xn0 = 0.f, xn1 = 0.f, xn2 = 0.f, xn3 = 0.f;
        if (lane < 16 && Lu == 0 && t < T_STEPS - 2){
            const float* xq = g_x1 + ((size_t)(t + 2) * BATCH + b0 + bu) * GATES + j_glob;
            xn0 = xq[0]; xn1 = xq[128]; xn2 = xq[256]; xn3 = xq[384];
        }

        // dot products: 32 LDS.128, 192 fma2
        const ulonglong2* A0 = (const ulonglong2*)&h1s[cur][0][c * HPAD];
        const ulonglong2* A1 = (const ulonglong2*)&h1s[cur][1][c * HPAD];
        const ulonglong2* D0 = (const ulonglong2*)&h2s[cur][0][c * HPAD];
        const ulonglong2* D1 = (const ulonglong2*)&h2s[cur][1][c * HPAD];
        unsigned long long a1[2][2] = {{0ull,0ull},{0ull,0ull}};
        unsigned long long a2[2][2] = {{0ull,0ull},{0ull,0ull}};
        unsigned long long a3[2][2] = {{0ull,0ull},{0ull,0ull}};
        #pragma unroll
        for (int i = 0; i < 8; i++){
            ulonglong2 av0 = A0[i], av1 = A1[i], dv0 = D0[i], dv1 = D1[i];
            #pragma unroll
            for (int gg = 0; gg < 2; gg++){
                a1[gg][0] = fma2(w1p[gg][2*i], av0.x, a1[gg][0]);
                a1[gg][0] = fma2(w1p[gg][2*i+1], av0.y, a1[gg][0]);
                a1[gg][1] = fma2(w1p[gg][2*i], av1.x, a1[gg][1]);
                a1[gg][1] = fma2(w1p[gg][2*i+1], av1.y, a1[gg][1]);
                a2[gg][0] = fma2(w2p[gg][2*i], av0.x, a2[gg][0]);
                a2[gg][0] = fma2(w2p[gg][2*i+1], av0.y, a2[gg][0]);
                a2[gg][1] = fma2(w2p[gg][2*i], av1.x, a2[gg][1]);
                a2[gg][1] = fma2(w2p[gg][2*i+1], av1.y, a2[gg][1]);
                a3[gg][0] = fma2(w3p[gg][2*i], dv0.x, a3[gg][0]);
                a3[gg][0] = fma2(w3p[gg][2*i+1], dv0.y, a3[gg][0]);
                a3[gg][1] = fma2(w3p[gg][2*i], dv1.x, a3[gg][1]);
                a3[gg][1] = fma2(w3p[gg][2*i+1], dv1.y, a3[gg][1]);
            }
        }
        float S1[2][2], S23[2][2];
        #pragma unroll
        for (int gg = 0; gg < 2; gg++){
            #pragma unroll
            for (int bb = 0; bb < 2; bb++){
                S1[gg][bb]  = hsum2(a1[gg][bb]);
                S23[gg][bb] = hsum2(a2[gg][bb]) + hsum2(a3[gg][bb]);
            }
        }
        // quad reduction across the 4 k-chunks
        #pragma unroll
        for (int gg = 0; gg < 2; gg++){
            #pragma unroll
            for (int bb = 0; bb < 2; bb++){
                S1[gg][bb]  += __shfl_xor_sync(0xFFFFFFFFu, S1[gg][bb],  1);
                S1[gg][bb]  += __shfl_xor_sync(0xFFFFFFFFu, S1[gg][bb],  2);
                S23[gg][bb] += __shfl_xor_sync(0xFFFFFFFFu, S23[gg][bb], 1);
                S23[gg][bb] += __shfl_xor_sync(0xFFFFFFFFu, S23[gg][bb], 2);
            }
        }
        // gate-pair exchange: lane selects its (layer, batch), swaps with slot^4
        float v0 = Lu ? S23[0][bu] : S1[0][bu];   // gate 2gp+0
        float v1 = Lu ? S23[1][bu] : S1[1][bu];   // gate 2gp+1
        float v2 = __shfl_xor_sync(0xFFFFFFFFu, v0, 16);
        float v3 = __shfl_xor_sync(0xFFFFFFFFu, v1, 16);

        float outv = 0.f;
        int dow = 0;
        if (lane < 16){
            if (Lu == 0){
                // always compute+store (t=T-1 value unused)
                float p0 = v0 + xu0, p1 = v1 + xu1, p2 = v2 + xu2, p3 = v3 + xu3;
                float cn = sigf(p1) * cst + sigf(p0) * tanhfast(p2);
                cst = cn;
                float h = sigf(p3) * tanhfast(cn);
                h1s[nxt][bu][(int)rank * HPAD + j_cta] = h;
            } else {
                float p0 = v0 + b2r0, p1 = v1 + b2r1, p2 = v2 + b2r2, p3 = v3 + b2r3;
                float cn = sigf(p1) * cst + sigf(p0) * tanhfast(p2);
                cst = cn;
                float h = sigf(p3) * tanhfast(cn);
                h2s[nxt][bu][(int)rank * HPAD + j_cta] = h;
                outv = h; dow = 1;
            }
        }
        if (dow)
            out[((size_t)(b0 + bu) * T_STEPS + t) * HID + j_glob] = outv;
        xu0 = xn0; xu1 = xn1; xu2 = xn2; xu3 = xn3;

        // local STS visible CTA-wide, then 12 bulk copies to the 3 peers
        __syncthreads();
        if (lane < 2 && w < 6){
            uint32_t blk = (uint32_t)__cvta_generic_to_shared(cp_arr
                ? &h2s[nxt][cp_bu][(int)rank * HPAD]
                : &h1s[nxt][cp_bu][(int)rank * HPAD]);
            bulk128(blk, mbt, cp_pr);
        }

        // wait for the 3 peers' 1536B; re-arm for this barrier's next use (t+2)
        int par = (t >> 1) & 1;
        if (!b) par ^= 1;
        mbar_wait_c(mbt, (uint32_t)par);
        if (tid == 0) mbar_expect(mbt, 1536u);
        cur = nxt;
    }
}

// ---------------------------------------------------------------------------
extern "C" void kernel_launch(void* const* d_in, const int* in_sizes, int n_in,
                              void* d_out, int out_size)
{
    (void)in_sizes; (void)n_in; (void)out_size;
    const float* feats = (const float*)d_in[0];
    const float* W_ih1 = (const float*)d_in[1];
    const float* W_hh1 = (const float*)d_in[2];
    const float* b_ih1 = (const float*)d_in[3];
    const float* b_hh1 = (const float*)d_in[4];
    const float* W_ih2 = (const float*)d_in[5];
    const float* W_hh2 = (const float*)d_in[6];
    const float* b_ih2 = (const float*)d_in[7];
    const float* b_hh2 = (const float*)d_in[8];
    float* out = (float*)d_out;

    cudaFuncSetAttribute(x1_gemm_hmma, cudaFuncAttributeMaxDynamicSharedMemorySize, GSMEM);

    dim3 g1(GATES / 128, (BATCH * T_STEPS) / 128);   // (4, 256)
    x1_gemm_hmma<<<g1, 256, GSMEM>>>(feats, W_ih1, b_ih1, b_hh1);

    lstm_rec_kernel<<<128, 256>>>(W_hh1, W_ih2, W_hh2, b_ih2, b_hh2, out);
}